// round 1
// baseline (speedup 1.0000x reference)
#include <cuda_runtime.h>
#include <math.h>

#define D    1024
#define NV   128
#define BATCH 32768

// Scratch (static device globals — no allocation in kernel_launch)
__device__ float g_U [D * NV];     // normalized reflectors, column layout U[d*NV+k]
__device__ float g_Ut[NV * D];     // transposed copy Ut[k*D+d]
__device__ float g_G [NV * NV];    // Gram matrix G = U^T U
__device__ float g_M [NV * NV];    // M = 2*T (WY factor)
__device__ float g_Z [BATCH * NV]; // Z = (x U) M   (16 MB)

// ---------------------------------------------------------------------------
// Kernel 1: normalize columns of v -> U and U^T
// ---------------------------------------------------------------------------
__global__ void k_norm(const float* __restrict__ v) {
    const int k   = blockIdx.x;
    const int tid = threadIdx.x;
    __shared__ float red[256];

    float s = 0.f;
    for (int d = tid; d < D; d += 256) {
        float t = v[d * NV + k];
        s += t * t;
    }
    red[tid] = s;
    __syncthreads();
    for (int off = 128; off > 0; off >>= 1) {
        if (tid < off) red[tid] += red[tid + off];
        __syncthreads();
    }
    const float inv = 1.0f / sqrtf(red[0]);
    for (int d = tid; d < D; d += 256) {
        float u = v[d * NV + k] * inv;
        g_U[d * NV + k] = u;
        g_Ut[k * D + d] = u;
    }
}

// ---------------------------------------------------------------------------
// Kernel 2: G = U^T U   (128x128, K=1024) — tiny
// ---------------------------------------------------------------------------
__global__ void k_gram() {
    const int j = blockIdx.x;
    const int i = threadIdx.x;
    float acc = 0.f;
#pragma unroll 8
    for (int d = 0; d < D; d++)
        acc += g_U[d * NV + i] * g_U[d * NV + j];
    g_G[i * NV + j] = acc;
}

// ---------------------------------------------------------------------------
// Kernel 3: build M = 2*T via the WY recurrence, single CTA of 128 threads.
//   T[0:m, m] = -2 * T_{m-1} @ G[0:m, m], diag(T) = 1
// ---------------------------------------------------------------------------
__global__ void k_buildM() {
    extern __shared__ float sT[];       // 128 * 129 floats (row-padded)
    __shared__ float gcol[NV];
    const int tid = threadIdx.x;        // 0..127 = row index

    for (int j = 0; j < NV; j++)
        sT[tid * 129 + j] = (tid == j) ? 1.f : 0.f;
    __syncthreads();

    for (int m = 1; m < NV; m++) {
        gcol[tid] = g_G[tid * NV + m];
        __syncthreads();
        float acc = 0.f;
        if (tid < m) {
            for (int j = tid; j < m; j++)
                acc += sT[tid * 129 + j] * gcol[j];
        }
        __syncthreads();
        if (tid < m) sT[tid * 129 + m] = -2.f * acc;
        __syncthreads();
    }

    for (int j = 0; j < NV; j++)
        g_M[tid * NV + j] = 2.f * sT[tid * 129 + j];
}

// ---------------------------------------------------------------------------
// Kernel 4: fused  Y = x @ U (64x128 tile, K=1024)  then  Z = Y @ M (K=128)
// 256 threads, 4x8 register tile per thread.
// ---------------------------------------------------------------------------
__global__ void k_yz(const float* __restrict__ x) {
    const int tid = threadIdx.x;
    const int tx  = tid & 15;       // 0..15 -> 8 output cols each
    const int ty  = tid >> 4;       // 0..15 -> 4 output rows each
    const int rowBase = blockIdx.x * 64;

    extern __shared__ float sm[];
    float* xbuf = sm;                 // 64*33  = 2112 floats
    float* ubuf = sm + 2112;          // 32*128 = 4096 floats (also M chunks)
    float* ybuf = sm + 2112 + 4096;   // 64*129 = 8256 floats

    float acc[4][8];
#pragma unroll
    for (int r = 0; r < 4; r++)
#pragma unroll
        for (int c = 0; c < 8; c++) acc[r][c] = 0.f;

    // ---- stage 1: Y = x @ U over K=1024 in chunks of 32 ----
    for (int kt = 0; kt < D / 32; kt++) {
#pragma unroll
        for (int it = 0; it < 2; it++) {            // x tile 64x32
            int q   = tid + it * 256;
            int row = q >> 3;
            int c4  = q & 7;
            float4 t = *(const float4*)&x[(size_t)(rowBase + row) * D + kt * 32 + c4 * 4];
            float* dst = &xbuf[row * 33 + c4 * 4];
            dst[0] = t.x; dst[1] = t.y; dst[2] = t.z; dst[3] = t.w;
        }
#pragma unroll
        for (int it = 0; it < 4; it++) {            // U tile 32x128
            int q  = tid + it * 256;
            int kr = q >> 5;
            int c4 = q & 31;
            *(float4*)&ubuf[kr * 128 + c4 * 4] =
                *(const float4*)&g_U[(kt * 32 + kr) * NV + c4 * 4];
        }
        __syncthreads();
#pragma unroll
        for (int kk = 0; kk < 32; kk++) {
            float aa[4];
#pragma unroll
            for (int r = 0; r < 4; r++) aa[r] = xbuf[(ty * 4 + r) * 33 + kk];
            float4 b0 = *(float4*)&ubuf[kk * 128 + tx * 8];
            float4 b1 = *(float4*)&ubuf[kk * 128 + tx * 8 + 4];
            float bb[8] = {b0.x, b0.y, b0.z, b0.w, b1.x, b1.y, b1.z, b1.w};
#pragma unroll
            for (int r = 0; r < 4; r++)
#pragma unroll
                for (int c = 0; c < 8; c++) acc[r][c] += aa[r] * bb[c];
        }
        __syncthreads();
    }

    // ---- Y -> shared ----
#pragma unroll
    for (int r = 0; r < 4; r++)
#pragma unroll
        for (int c = 0; c < 8; c++)
            ybuf[(ty * 4 + r) * 129 + tx * 8 + c] = acc[r][c];
    __syncthreads();

    // ---- stage 2: Z = Y @ M over K=128 in chunks of 32 ----
    float zacc[4][8];
#pragma unroll
    for (int r = 0; r < 4; r++)
#pragma unroll
        for (int c = 0; c < 8; c++) zacc[r][c] = 0.f;

    for (int mt = 0; mt < 4; mt++) {
#pragma unroll
        for (int it = 0; it < 4; it++) {            // M chunk 32x128
            int q  = tid + it * 256;
            int kr = q >> 5;
            int c4 = q & 31;
            *(float4*)&ubuf[kr * 128 + c4 * 4] =
                *(const float4*)&g_M[(mt * 32 + kr) * NV + c4 * 4];
        }
        __syncthreads();
#pragma unroll
        for (int kk = 0; kk < 32; kk++) {
            float yy[4];
#pragma unroll
            for (int r = 0; r < 4; r++) yy[r] = ybuf[(ty * 4 + r) * 129 + mt * 32 + kk];
            float4 m0 = *(float4*)&ubuf[kk * 128 + tx * 8];
            float4 m1 = *(float4*)&ubuf[kk * 128 + tx * 8 + 4];
            float mm[8] = {m0.x, m0.y, m0.z, m0.w, m1.x, m1.y, m1.z, m1.w};
#pragma unroll
            for (int r = 0; r < 4; r++)
#pragma unroll
                for (int c = 0; c < 8; c++) zacc[r][c] += yy[r] * mm[c];
        }
        __syncthreads();
    }

    // ---- write Z ----
#pragma unroll
    for (int r = 0; r < 4; r++) {
        float4 o0 = {zacc[r][0], zacc[r][1], zacc[r][2], zacc[r][3]};
        float4 o1 = {zacc[r][4], zacc[r][5], zacc[r][6], zacc[r][7]};
        size_t base = (size_t)(rowBase + ty * 4 + r) * NV + tx * 8;
        *(float4*)&g_Z[base]     = o0;
        *(float4*)&g_Z[base + 4] = o1;
    }
}

// ---------------------------------------------------------------------------
// Kernel 5: out = x - Z @ U^T + b   (64x128 output tile, K=128)
// ---------------------------------------------------------------------------
__global__ void k_out(const float* __restrict__ x, const float* __restrict__ b,
                      float* __restrict__ out) {
    const int tid = threadIdx.x;
    const int tx  = tid & 15;
    const int ty  = tid >> 4;
    const int rowBase = blockIdx.x * 64;
    const int dB      = blockIdx.y * 128;

    extern __shared__ float sm[];
    float* zs = sm;            // 64*129 = 8256 floats
    float* bs = sm + 8256;     // 32*128 = 4096 floats

    // load Z tile 64x128
#pragma unroll
    for (int it = 0; it < 8; it++) {
        int q   = tid + it * 256;
        int row = q >> 5;
        int c4  = q & 31;
        float4 t = *(const float4*)&g_Z[(size_t)(rowBase + row) * NV + c4 * 4];
        float* dst = &zs[row * 129 + c4 * 4];
        dst[0] = t.x; dst[1] = t.y; dst[2] = t.z; dst[3] = t.w;
    }

    float acc[4][8];
#pragma unroll
    for (int r = 0; r < 4; r++)
#pragma unroll
        for (int c = 0; c < 8; c++) acc[r][c] = 0.f;

    for (int mt = 0; mt < 4; mt++) {
#pragma unroll
        for (int it = 0; it < 4; it++) {   // Ut chunk 32 x 128 (rows k, cols d)
            int q  = tid + it * 256;
            int kr = q >> 5;
            int c4 = q & 31;
            *(float4*)&bs[kr * 128 + c4 * 4] =
                *(const float4*)&g_Ut[(size_t)(mt * 32 + kr) * D + dB + c4 * 4];
        }
        __syncthreads();
#pragma unroll
        for (int kk = 0; kk < 32; kk++) {
            float zz[4];
#pragma unroll
            for (int r = 0; r < 4; r++) zz[r] = zs[(ty * 4 + r) * 129 + mt * 32 + kk];
            float4 u0 = *(float4*)&bs[kk * 128 + tx * 8];
            float4 u1 = *(float4*)&bs[kk * 128 + tx * 8 + 4];
            float uu[8] = {u0.x, u0.y, u0.z, u0.w, u1.x, u1.y, u1.z, u1.w};
#pragma unroll
            for (int r = 0; r < 4; r++)
#pragma unroll
                for (int c = 0; c < 8; c++) acc[r][c] += zz[r] * uu[c];
        }
        __syncthreads();
    }

    // epilogue: out = x + b - acc
    const int gcol = dB + tx * 8;
    float4 b0 = *(const float4*)&b[gcol];
    float4 b1 = *(const float4*)&b[gcol + 4];
#pragma unroll
    for (int r = 0; r < 4; r++) {
        size_t base = (size_t)(rowBase + ty * 4 + r) * D + gcol;
        float4 x0 = *(const float4*)&x[base];
        float4 x1 = *(const float4*)&x[base + 4];
        float4 o0, o1;
        o0.x = x0.x + b0.x - acc[r][0];
        o0.y = x0.y + b0.y - acc[r][1];
        o0.z = x0.z + b0.z - acc[r][2];
        o0.w = x0.w + b0.w - acc[r][3];
        o1.x = x1.x + b1.x - acc[r][4];
        o1.y = x1.y + b1.y - acc[r][5];
        o1.z = x1.z + b1.z - acc[r][6];
        o1.w = x1.w + b1.w - acc[r][7];
        *(float4*)&out[base]     = o0;
        *(float4*)&out[base + 4] = o1;
    }
}

// ---------------------------------------------------------------------------
extern "C" void kernel_launch(void* const* d_in, const int* in_sizes, int n_in,
                              void* d_out, int out_size) {
    const float* x = nullptr;
    const float* v = nullptr;
    const float* b = nullptr;
    for (int i = 0; i < n_in; i++) {
        if      (in_sizes[i] == BATCH * D) x = (const float*)d_in[i];
        else if (in_sizes[i] == D * NV)    v = (const float*)d_in[i];
        else if (in_sizes[i] == D)         b = (const float*)d_in[i];
    }
    float* out = (float*)d_out;

    cudaFuncSetAttribute(k_buildM, cudaFuncAttributeMaxDynamicSharedMemorySize, 128 * 129 * 4);
    cudaFuncSetAttribute(k_yz,     cudaFuncAttributeMaxDynamicSharedMemorySize, (2112 + 4096 + 8256) * 4);
    cudaFuncSetAttribute(k_out,    cudaFuncAttributeMaxDynamicSharedMemorySize, (8256 + 4096) * 4);

    k_norm  <<<NV, 256>>>(v);
    k_gram  <<<NV, NV>>>();
    k_buildM<<<1, NV, 128 * 129 * 4>>>();
    k_yz    <<<BATCH / 64, 256, (2112 + 4096 + 8256) * 4>>>(x);
    k_out   <<<dim3(BATCH / 64, D / 128), 256, (8256 + 4096) * 4>>>(x, b, out);
}

// round 2
// speedup vs baseline: 2.1887x; 2.1887x over previous
#include <cuda_runtime.h>
#include <math.h>

#define D     1024
#define NV    128
#define BATCH 32768

// Scratch (static device globals — no allocation in kernel_launch)
__device__ float g_U [D * NV];     // normalized reflectors, U[d*NV+k]
__device__ float g_Ut[NV * D];     // transposed, Ut[k*D+d]
__device__ float g_G [NV * NV];    // Gram G = U^T U
__device__ float g_M [NV * NV];    // M = 2*T (WY factor)

// ---------------------------------------------------------------------------
// Kernel 1: normalize columns of v -> U and U^T
// ---------------------------------------------------------------------------
__global__ void k_norm(const float* __restrict__ v) {
    const int k   = blockIdx.x;
    const int tid = threadIdx.x;
    __shared__ float red[256];

    float s = 0.f;
    for (int d = tid; d < D; d += 256) {
        float t = v[d * NV + k];
        s += t * t;
    }
    red[tid] = s;
    __syncthreads();
    for (int off = 128; off > 0; off >>= 1) {
        if (tid < off) red[tid] += red[tid + off];
        __syncthreads();
    }
    const float inv = 1.0f / sqrtf(red[0]);
    for (int d = tid; d < D; d += 256) {
        float u = v[d * NV + k] * inv;
        g_U[d * NV + k] = u;
        g_Ut[k * D + d] = u;
    }
}

// ---------------------------------------------------------------------------
// Kernel 2: G = U^T U   (128x128, K=1024)
// ---------------------------------------------------------------------------
__global__ void k_gram() {
    const int j = blockIdx.x;
    const int i = threadIdx.x;
    float acc = 0.f;
#pragma unroll 8
    for (int d = 0; d < D; d++)
        acc += g_U[d * NV + i] * g_U[d * NV + j];
    g_G[i * NV + j] = acc;
}

// ---------------------------------------------------------------------------
// Kernel 3: M = 2*T via WY recurrence, single CTA of 128 threads.
// ---------------------------------------------------------------------------
__global__ void k_buildM() {
    extern __shared__ float sT[];       // 128 * 129 floats
    __shared__ float gcol[NV];
    const int tid = threadIdx.x;

    for (int j = 0; j < NV; j++)
        sT[tid * 129 + j] = (tid == j) ? 1.f : 0.f;
    __syncthreads();

    for (int m = 1; m < NV; m++) {
        gcol[tid] = g_G[tid * NV + m];
        __syncthreads();
        float acc = 0.f;
        if (tid < m) {
            for (int j = tid; j < m; j++)
                acc += sT[tid * 129 + j] * gcol[j];
        }
        __syncthreads();
        if (tid < m) sT[tid * 129 + m] = -2.f * acc;
        __syncthreads();
    }

    for (int j = 0; j < NV; j++)
        g_M[tid * NV + j] = 2.f * sT[tid * 129 + j];
}

// ---------------------------------------------------------------------------
// Fused tensor-core kernel (tf32 mma.sync m16n8k8):
//   Y = x U  (K=1024)  ->  Z = Y M (K=128, smem-resident)  ->
//   out = x - Z U^T + b  (8 chunks of 128 output cols)
// CTA: 128 rows, 256 threads (8 warps, 2x4), warp tile 64x32.
// ---------------------------------------------------------------------------
#define XS 36     // xs row stride (words)
#define US 132    // us row stride
#define YS 132    // ys row stride

__device__ __forceinline__ unsigned f2tf(float f) {
    unsigned r;
    asm("cvt.rna.tf32.f32 %0, %1;" : "=r"(r) : "f"(f));
    return r;
}

__device__ __forceinline__ void mma8(float c[4], const unsigned a[4], const unsigned b[2]) {
    asm volatile(
        "mma.sync.aligned.m16n8k8.row.col.f32.tf32.tf32.f32 "
        "{%0,%1,%2,%3}, {%4,%5,%6,%7}, {%8,%9}, {%0,%1,%2,%3};"
        : "+f"(c[0]), "+f"(c[1]), "+f"(c[2]), "+f"(c[3])
        : "r"(a[0]), "r"(a[1]), "r"(a[2]), "r"(a[3]), "r"(b[0]), "r"(b[1]));
}

__global__ __launch_bounds__(256, 2) void k_fused(const float* __restrict__ x,
                                                  const float* __restrict__ bias,
                                                  float* __restrict__ out) {
    extern __shared__ float sm[];
    float* xs = sm;            // 128*36  = 4608 f
    float* us = sm + 4608;     // 32*132  = 4224 f
    float* ys = sm + 8832;     // 128*132 = 16896 f

    const int tid  = threadIdx.x;
    const int lane = tid & 31, wid = tid >> 5;
    const int wm = wid >> 2, wn = wid & 3;          // 2 x 4 warp grid
    const int grp = lane >> 2, tg = lane & 3;
    const int rowBase = blockIdx.x * 128;
    const int wrow = wm * 64;
    const int wcol = wn * 32;

    float acc[4][4][4];

    // ======== Stage 1: Y = x @ U ========
#pragma unroll
    for (int mf = 0; mf < 4; mf++)
#pragma unroll
        for (int nf = 0; nf < 4; nf++)
#pragma unroll
            for (int q = 0; q < 4; q++) acc[mf][nf][q] = 0.f;

    for (int kt = 0; kt < D / 32; kt++) {
#pragma unroll
        for (int it = 0; it < 4; it++) {            // x tile 128x32
            int q = tid + it * 256;
            int row = q >> 3, c4 = q & 7;
            *(float4*)&xs[row * XS + c4 * 4] =
                *(const float4*)&x[(size_t)(rowBase + row) * D + kt * 32 + c4 * 4];
        }
#pragma unroll
        for (int it = 0; it < 4; it++) {            // U tile 32x128
            int q = tid + it * 256;
            int kr = q >> 5, c4 = q & 31;
            *(float4*)&us[kr * US + c4 * 4] =
                *(const float4*)&g_U[(kt * 32 + kr) * NV + c4 * 4];
        }
        __syncthreads();
#pragma unroll
        for (int k8 = 0; k8 < 4; k8++) {
            const int kb = k8 * 8;
            unsigned A[4][4], Bf[4][2];
#pragma unroll
            for (int mf = 0; mf < 4; mf++) {
                int r = wrow + mf * 16 + grp;
                A[mf][0] = f2tf(xs[r * XS + kb + tg]);
                A[mf][1] = f2tf(xs[(r + 8) * XS + kb + tg]);
                A[mf][2] = f2tf(xs[r * XS + kb + tg + 4]);
                A[mf][3] = f2tf(xs[(r + 8) * XS + kb + tg + 4]);
            }
#pragma unroll
            for (int nf = 0; nf < 4; nf++) {
                int c = wcol + nf * 8 + grp;
                Bf[nf][0] = f2tf(us[(kb + tg) * US + c]);
                Bf[nf][1] = f2tf(us[(kb + tg + 4) * US + c]);
            }
#pragma unroll
            for (int mf = 0; mf < 4; mf++)
#pragma unroll
                for (int nf = 0; nf < 4; nf++)
                    mma8(acc[mf][nf], A[mf], Bf[nf]);
        }
        __syncthreads();
    }

    // Y -> ys
#pragma unroll
    for (int mf = 0; mf < 4; mf++)
#pragma unroll
        for (int nf = 0; nf < 4; nf++) {
            int r = wrow + mf * 16 + grp, c = wcol + nf * 8 + tg * 2;
            ys[r * YS + c]           = acc[mf][nf][0];
            ys[r * YS + c + 1]       = acc[mf][nf][1];
            ys[(r + 8) * YS + c]     = acc[mf][nf][2];
            ys[(r + 8) * YS + c + 1] = acc[mf][nf][3];
        }
    __syncthreads();

    // ======== Stage 2: Z = Y @ M ========
#pragma unroll
    for (int mf = 0; mf < 4; mf++)
#pragma unroll
        for (int nf = 0; nf < 4; nf++)
#pragma unroll
            for (int q = 0; q < 4; q++) acc[mf][nf][q] = 0.f;

    for (int mt = 0; mt < 4; mt++) {
#pragma unroll
        for (int it = 0; it < 4; it++) {            // M chunk 32x128
            int q = tid + it * 256;
            int kr = q >> 5, c4 = q & 31;
            *(float4*)&us[kr * US + c4 * 4] =
                *(const float4*)&g_M[(mt * 32 + kr) * NV + c4 * 4];
        }
        __syncthreads();
#pragma unroll
        for (int k8 = 0; k8 < 4; k8++) {
            const int kb = k8 * 8;
            const int kg = mt * 32 + kb;
            unsigned A[4][4], Bf[4][2];
#pragma unroll
            for (int mf = 0; mf < 4; mf++) {
                int r = wrow + mf * 16 + grp;
                A[mf][0] = f2tf(ys[r * YS + kg + tg]);
                A[mf][1] = f2tf(ys[(r + 8) * YS + kg + tg]);
                A[mf][2] = f2tf(ys[r * YS + kg + tg + 4]);
                A[mf][3] = f2tf(ys[(r + 8) * YS + kg + tg + 4]);
            }
#pragma unroll
            for (int nf = 0; nf < 4; nf++) {
                int c = wcol + nf * 8 + grp;
                Bf[nf][0] = f2tf(us[(kb + tg) * US + c]);
                Bf[nf][1] = f2tf(us[(kb + tg + 4) * US + c]);
            }
#pragma unroll
            for (int mf = 0; mf < 4; mf++)
#pragma unroll
                for (int nf = 0; nf < 4; nf++)
                    mma8(acc[mf][nf], A[mf], Bf[nf]);
        }
        __syncthreads();
    }

    // Z overwrites Y in ys (all reads of Y completed at last sync)
#pragma unroll
    for (int mf = 0; mf < 4; mf++)
#pragma unroll
        for (int nf = 0; nf < 4; nf++) {
            int r = wrow + mf * 16 + grp, c = wcol + nf * 8 + tg * 2;
            ys[r * YS + c]           = acc[mf][nf][0];
            ys[r * YS + c + 1]       = acc[mf][nf][1];
            ys[(r + 8) * YS + c]     = acc[mf][nf][2];
            ys[(r + 8) * YS + c + 1] = acc[mf][nf][3];
        }
    __syncthreads();

    // ======== Stage 3: out = x - Z @ U^T + b ========
    for (int dB = 0; dB < D; dB += 128) {
#pragma unroll
        for (int mf = 0; mf < 4; mf++)
#pragma unroll
            for (int nf = 0; nf < 4; nf++)
#pragma unroll
                for (int q = 0; q < 4; q++) acc[mf][nf][q] = 0.f;

        for (int mt = 0; mt < 4; mt++) {
#pragma unroll
            for (int it = 0; it < 4; it++) {        // Ut chunk 32x128
                int q = tid + it * 256;
                int kr = q >> 5, c4 = q & 31;
                *(float4*)&us[kr * US + c4 * 4] =
                    *(const float4*)&g_Ut[(size_t)(mt * 32 + kr) * D + dB + c4 * 4];
            }
            __syncthreads();
#pragma unroll
            for (int k8 = 0; k8 < 4; k8++) {
                const int kb = k8 * 8;
                const int kg = mt * 32 + kb;
                unsigned A[4][4], Bf[4][2];
#pragma unroll
                for (int mf = 0; mf < 4; mf++) {
                    int r = wrow + mf * 16 + grp;
                    A[mf][0] = f2tf(ys[r * YS + kg + tg]);
                    A[mf][1] = f2tf(ys[(r + 8) * YS + kg + tg]);
                    A[mf][2] = f2tf(ys[r * YS + kg + tg + 4]);
                    A[mf][3] = f2tf(ys[(r + 8) * YS + kg + tg + 4]);
                }
#pragma unroll
                for (int nf = 0; nf < 4; nf++) {
                    int c = wcol + nf * 8 + grp;
                    Bf[nf][0] = f2tf(us[(kb + tg) * US + c]);
                    Bf[nf][1] = f2tf(us[(kb + tg + 4) * US + c]);
                }
#pragma unroll
                for (int mf = 0; mf < 4; mf++)
#pragma unroll
                    for (int nf = 0; nf < 4; nf++)
                        mma8(acc[mf][nf], A[mf], Bf[nf]);
            }
            __syncthreads();
        }

        // epilogue: out = x + b - acc
#pragma unroll
        for (int mf = 0; mf < 4; mf++)
#pragma unroll
            for (int nf = 0; nf < 4; nf++) {
                int r = rowBase + wrow + mf * 16 + grp;
                int c = dB + wcol + nf * 8 + tg * 2;
                float2 bv = *(const float2*)&bias[c];
                float2 x0 = *(const float2*)&x[(size_t)r * D + c];
                float2 x1 = *(const float2*)&x[(size_t)(r + 8) * D + c];
                float2 o0, o1;
                o0.x = x0.x + bv.x - acc[mf][nf][0];
                o0.y = x0.y + bv.y - acc[mf][nf][1];
                o1.x = x1.x + bv.x - acc[mf][nf][2];
                o1.y = x1.y + bv.y - acc[mf][nf][3];
                *(float2*)&out[(size_t)r * D + c]       = o0;
                *(float2*)&out[(size_t)(r + 8) * D + c] = o1;
            }
    }
}

// ---------------------------------------------------------------------------
extern "C" void kernel_launch(void* const* d_in, const int* in_sizes, int n_in,
                              void* d_out, int out_size) {
    const float* x = nullptr;
    const float* v = nullptr;
    const float* b = nullptr;
    for (int i = 0; i < n_in; i++) {
        if      (in_sizes[i] == BATCH * D) x = (const float*)d_in[i];
        else if (in_sizes[i] == D * NV)    v = (const float*)d_in[i];
        else if (in_sizes[i] == D)         b = (const float*)d_in[i];
    }
    float* out = (float*)d_out;

    const size_t smemFused = (4608 + 4224 + 16896) * sizeof(float);  // ~102.9 KB
    cudaFuncSetAttribute(k_buildM, cudaFuncAttributeMaxDynamicSharedMemorySize, 128 * 129 * 4);
    cudaFuncSetAttribute(k_fused,  cudaFuncAttributeMaxDynamicSharedMemorySize, (int)smemFused);

    k_norm  <<<NV, 256>>>(v);
    k_gram  <<<NV, NV>>>();
    k_buildM<<<1, NV, 128 * 129 * 4>>>();
    k_fused <<<BATCH / 128, 256, smemFused>>>(x, b, out);
}